// round 1
// baseline (speedup 1.0000x reference)
#include <cuda_runtime.h>

#define NN   64
#define CC   128
#define HWP  3136          // 56*56
#define MTOT 200704        // NN*HWP
#define EPSI 1e-5f
#define TITER 10
#define NS_BLOCKS 128
#define CHUNK 784          // HWP/4, multiple of 16

// ---------------- scratch (device globals; no allocation) ----------------
__device__ float d_gram[CC * CC];
__device__ float d_chsum[CC];
__device__ float d_Sig[CC * CC];
__device__ float d_P[CC * CC];
__device__ float d_wmT[CC * CC];
__device__ float d_bias2[CC];
__device__ float d_trace;
__device__ unsigned g_bar;

// ---------------- packed fp32x2 helpers (sm_103a dual-FMA) ----------------
__device__ __forceinline__ unsigned long long pk(float lo, float hi) {
    unsigned long long r;
    asm("mov.b64 %0, {%1, %2};" : "=l"(r) : "f"(lo), "f"(hi));
    return r;
}
__device__ __forceinline__ void unpk(unsigned long long v, float &lo, float &hi) {
    asm("mov.b64 {%0, %1}, %2;" : "=f"(lo), "=f"(hi) : "l"(v));
}
__device__ __forceinline__ void fma2(unsigned long long &d, unsigned long long a, unsigned long long b) {
    asm("fma.rn.f32x2 %0, %1, %2, %0;" : "+l"(d) : "l"(a), "l"(b));
}

// ---------------- kernel 0: zero scratch (runs every launch) ----------------
__global__ void zero_kernel() {
    int i = blockIdx.x * 256 + threadIdx.x;
    if (i < CC * CC) d_gram[i] = 0.f;
    if (i < CC) d_chsum[i] = 0.f;
    if (i == 0) { d_trace = 0.f; g_bar = 0u; }
}

// ---------------- kernel 1: Gram matrix + channel sums ----------------
// 256 blocks: block = (n, p-chunk of 784). Full 128x128 tile per block,
// 256 threads, 16(rows)x4(cols) register tile, f32x2 pairs along rows.
__global__ void __launch_bounds__(256, 2) gram_kernel(const float* __restrict__ X) {
    __shared__ float As[16 * 132];
    __shared__ float chs[CC];
    const int tid = threadIdx.x;
    const int n = blockIdx.x >> 2;
    const int pbase = (blockIdx.x & 3) * CHUNK;
    const float* Xn = X + (size_t)n * (CC * HWP) + pbase;

    const int cL = tid >> 2;           // channel 0..63 (and cL+64)
    const int q0 = (tid & 3) * 4;      // kk group
    const int ty = tid >> 5;           // 0..7  -> rows ty*16..+15
    const int tx = tid & 31;           // 0..31 -> cols tx*4..+3

    unsigned long long acc[8][4];
#pragma unroll
    for (int i = 0; i < 8; i++)
#pragma unroll
        for (int j = 0; j < 4; j++) acc[i][j] = 0ull;
    float cs0 = 0.f, cs1 = 0.f;
    if (tid < CC) chs[tid] = 0.f;

    for (int ks = 0; ks < CHUNK; ks += 16) {
        __syncthreads();
        float4 v0 = *(const float4*)(Xn + (size_t)cL * HWP + ks + q0);
        float4 v1 = *(const float4*)(Xn + (size_t)(cL + 64) * HWP + ks + q0);
        As[(q0 + 0) * 132 + cL] = v0.x;
        As[(q0 + 1) * 132 + cL] = v0.y;
        As[(q0 + 2) * 132 + cL] = v0.z;
        As[(q0 + 3) * 132 + cL] = v0.w;
        As[(q0 + 0) * 132 + cL + 64] = v1.x;
        As[(q0 + 1) * 132 + cL + 64] = v1.y;
        As[(q0 + 2) * 132 + cL + 64] = v1.z;
        As[(q0 + 3) * 132 + cL + 64] = v1.w;
        cs0 += (v0.x + v0.y) + (v0.z + v0.w);
        cs1 += (v1.x + v1.y) + (v1.z + v1.w);
        __syncthreads();
#pragma unroll
        for (int k = 0; k < 16; k++) {
            const float* row = As + k * 132;
            ulonglong2 aA = *(const ulonglong2*)(row + ty * 16);
            ulonglong2 aB = *(const ulonglong2*)(row + ty * 16 + 4);
            ulonglong2 aC = *(const ulonglong2*)(row + ty * 16 + 8);
            ulonglong2 aD = *(const ulonglong2*)(row + ty * 16 + 12);
            float4 bv = *(const float4*)(row + tx * 4);
            unsigned long long b0 = pk(bv.x, bv.x);
            unsigned long long b1 = pk(bv.y, bv.y);
            unsigned long long b2 = pk(bv.z, bv.z);
            unsigned long long b3 = pk(bv.w, bv.w);
            unsigned long long ap[8] = {aA.x, aA.y, aB.x, aB.y, aC.x, aC.y, aD.x, aD.y};
#pragma unroll
            for (int ip = 0; ip < 8; ip++) {
                fma2(acc[ip][0], ap[ip], b0);
                fma2(acc[ip][1], ap[ip], b1);
                fma2(acc[ip][2], ap[ip], b2);
                fma2(acc[ip][3], ap[ip], b3);
            }
        }
    }
    // channel sums -> global
    __syncthreads();
    atomicAdd(&chs[cL], cs0);
    atomicAdd(&chs[cL + 64], cs1);
    __syncthreads();
    if (tid < CC) atomicAdd(&d_chsum[tid], chs[tid]);
    // gram tile -> global (atomic accumulate across 256 blocks)
#pragma unroll
    for (int ip = 0; ip < 8; ip++) {
        int r0 = ty * 16 + ip * 2;
#pragma unroll
        for (int jj = 0; jj < 4; jj++) {
            float lo, hi;
            unpk(acc[ip][jj], lo, hi);
            atomicAdd(&d_gram[r0 * CC + tx * 4 + jj], lo);
            atomicAdd(&d_gram[(r0 + 1) * CC + tx * 4 + jj], hi);
        }
    }
}

// ---------------- kernel 2: Sigma + Newton-Schulz (persistent, grid barrier) ---
__device__ __forceinline__ void gsync(unsigned &tgt) {
    __threadfence();           // publish this thread's prior writes/atomics
    __syncthreads();
    tgt += NS_BLOCKS;
    if (threadIdx.x == 0) {
        atomicAdd(&g_bar, 1u);
        while (*(volatile unsigned*)&g_bar < tgt) {}
    }
    __syncthreads();
}

__device__ __forceinline__ float rowmat(const float* __restrict__ vec_s,
                                        const float* __restrict__ Mg, int j) {
    float a0 = 0.f, a1 = 0.f, a2 = 0.f, a3 = 0.f;
#pragma unroll
    for (int k = 0; k < CC; k += 4) {
        a0 += vec_s[k + 0] * __ldcg(&Mg[(k + 0) * CC + j]);
        a1 += vec_s[k + 1] * __ldcg(&Mg[(k + 1) * CC + j]);
        a2 += vec_s[k + 2] * __ldcg(&Mg[(k + 2) * CC + j]);
        a3 += vec_s[k + 3] * __ldcg(&Mg[(k + 3) * CC + j]);
    }
    return (a0 + a1) + (a2 + a3);
}

__global__ void __launch_bounds__(128, 1) ns_kernel(const float* __restrict__ beta) {
    __shared__ float mean_s[CC], pr_s[CC], t1_s[CC], t2_s[CC];
    __shared__ float rtr_s;
    const int r = blockIdx.x;
    const int j = threadIdx.x;

    mean_s[j] = d_chsum[j] * (1.f / (float)MTOT);
    __syncthreads();

    float sig = d_gram[r * CC + j] * (1.f / (float)MTOT) - mean_s[r] * mean_s[j]
                + ((j == r) ? EPSI : 0.f);
    __stcg(&d_Sig[r * CC + j], sig);
    __stcg(&d_P[r * CC + j], (j == r) ? 1.f : 0.f);
    if (j == r) atomicAdd(&d_trace, sig);

    unsigned tgt = 0;
    gsync(tgt);

    if (j == 0) rtr_s = 1.f / *(volatile float*)&d_trace;
    __syncthreads();
    const float rtr = rtr_s;

    for (int it = 0; it < TITER; it++) {
        pr_s[j] = __ldcg(&d_P[r * CC + j]);
        __syncthreads();
        t1_s[j] = rowmat(pr_s, d_P, j);       // T1 = P@P   (row r)
        __syncthreads();
        t2_s[j] = rowmat(t1_s, d_P, j);       // T2 = T1@P  (row r)
        __syncthreads();
        float u = rowmat(t2_s, d_Sig, j);     // U  = T2@Sigma (row r)
        gsync(tgt);                           // everyone done READING P
        __stcg(&d_P[r * CC + j], 1.5f * pr_s[j] - 0.5f * rtr * u);
        gsync(tgt);                           // everyone done WRITING P
    }

    float w = __ldcg(&d_P[r * CC + j]) * sqrtf(rtr);   // wm = P*sqrt(rTr)
    d_wmT[j * CC + r] = w;                              // transposed for GEMM2
    t1_s[j] = w * mean_s[j];
    __syncthreads();
    for (int s = 64; s > 0; s >>= 1) {
        if (j < s) t1_s[j] += t1_s[j + s];
        __syncthreads();
    }
    if (j == 0) d_bias2[r] = beta[r] - t1_s[0];
}

// ---------------- kernel 3: whitening GEMM Y = wm @ X + bias ----------------
// 1568 blocks = 49 p-tiles(64 wide) x 32 n-pairs (n, n+32). 128x128 tile,
// j-cols: first 64 from n0, last 64 from n1.
__global__ void __launch_bounds__(256, 2) whit_kernel(const float* __restrict__ X,
                                                      float* __restrict__ Y) {
    __shared__ float Ws[16 * 128];
    __shared__ float Xs[16 * 132];
    __shared__ float bias_s[CC];
    const int tid = threadIdx.x;
    const int pt = blockIdx.x % 49;
    const int np = blockIdx.x / 49;
    const int p0 = pt * 64;
    const float* Xa = X + (size_t)np * (CC * HWP) + p0;
    const float* Xb = X + (size_t)(np + 32) * (CC * HWP) + p0;
    float* Ya = Y + (size_t)np * (CC * HWP) + p0;
    float* Yb = Y + (size_t)(np + 32) * (CC * HWP) + p0;

    if (tid < CC) bias_s[tid] = d_bias2[tid];
    const int ty = tid >> 5, tx = tid & 31;
    const int kkA = tid >> 5;          // 0..7
    const int gA = tid & 31;           // 0..31 (float4 group of the 128 cols)

    unsigned long long acc[8][4];
#pragma unroll
    for (int i = 0; i < 8; i++)
#pragma unroll
        for (int jj = 0; jj < 4; jj++) acc[i][jj] = 0ull;

    for (int ks = 0; ks < CC; ks += 16) {
        __syncthreads();
        // stage wm^T (rows = d, cols = c) and X (rows = d, cols = j')
        float4 w0 = *(const float4*)(d_wmT + (size_t)(ks + kkA) * CC + gA * 4);
        float4 w1 = *(const float4*)(d_wmT + (size_t)(ks + kkA + 8) * CC + gA * 4);
        *(float4*)(Ws + kkA * 128 + gA * 4) = w0;
        *(float4*)(Ws + (kkA + 8) * 128 + gA * 4) = w1;
        const float* s0 = (gA < 16) ? (Xa + (size_t)(ks + kkA) * HWP + gA * 4)
                                    : (Xb + (size_t)(ks + kkA) * HWP + (gA - 16) * 4);
        const float* s1 = (gA < 16) ? (Xa + (size_t)(ks + kkA + 8) * HWP + gA * 4)
                                    : (Xb + (size_t)(ks + kkA + 8) * HWP + (gA - 16) * 4);
        float4 x0 = *(const float4*)s0;
        float4 x1 = *(const float4*)s1;
        *(float4*)(Xs + kkA * 132 + gA * 4) = x0;
        *(float4*)(Xs + (kkA + 8) * 132 + gA * 4) = x1;
        __syncthreads();
#pragma unroll
        for (int k = 0; k < 16; k++) {
            const float* wr = Ws + k * 128;
            ulonglong2 aA = *(const ulonglong2*)(wr + ty * 16);
            ulonglong2 aB = *(const ulonglong2*)(wr + ty * 16 + 4);
            ulonglong2 aC = *(const ulonglong2*)(wr + ty * 16 + 8);
            ulonglong2 aD = *(const ulonglong2*)(wr + ty * 16 + 12);
            float4 bv = *(const float4*)(Xs + k * 132 + tx * 4);
            unsigned long long b0 = pk(bv.x, bv.x);
            unsigned long long b1 = pk(bv.y, bv.y);
            unsigned long long b2 = pk(bv.z, bv.z);
            unsigned long long b3 = pk(bv.w, bv.w);
            unsigned long long ap[8] = {aA.x, aA.y, aB.x, aB.y, aC.x, aC.y, aD.x, aD.y};
#pragma unroll
            for (int ip = 0; ip < 8; ip++) {
                fma2(acc[ip][0], ap[ip], b0);
                fma2(acc[ip][1], ap[ip], b1);
                fma2(acc[ip][2], ap[ip], b2);
                fma2(acc[ip][3], ap[ip], b3);
            }
        }
    }
    // epilogue: unpack pairs, add bias, vectorized store
    float* baseY = (tx < 16) ? Ya : Yb;
    const int off = (tx < 16) ? tx * 4 : (tx - 16) * 4;
#pragma unroll
    for (int ip = 0; ip < 8; ip++) {
        float l0, h0, l1, h1, l2, h2, l3, h3;
        unpk(acc[ip][0], l0, h0);
        unpk(acc[ip][1], l1, h1);
        unpk(acc[ip][2], l2, h2);
        unpk(acc[ip][3], l3, h3);
        const int r0 = ty * 16 + 2 * ip;
        const float b0 = bias_s[r0], b1 = bias_s[r0 + 1];
        float4 o0 = make_float4(l0 + b0, l1 + b0, l2 + b0, l3 + b0);
        float4 o1 = make_float4(h0 + b1, h1 + b1, h2 + b1, h3 + b1);
        *(float4*)(baseY + (size_t)r0 * HWP + off) = o0;
        *(float4*)(baseY + (size_t)(r0 + 1) * HWP + off) = o1;
    }
}

// ---------------- launch ----------------
extern "C" void kernel_launch(void* const* d_in, const int* in_sizes, int n_in,
                              void* d_out, int out_size) {
    const float* X = (const float*)d_in[0];
    const float* beta = (const float*)d_in[1];
    float* Y = (float*)d_out;
    zero_kernel<<<64, 256>>>();
    gram_kernel<<<256, 256>>>(X);
    ns_kernel<<<NS_BLOCKS, 128>>>(beta);
    whit_kernel<<<49 * 32, 256>>>(X, Y);
}